// round 16
// baseline (speedup 1.0000x reference)
#include <cuda_runtime.h>
#include <cstdint>

// ---------------- problem constants ----------------
#define S  2048
#define E  1024
#define H  1024
#define V  32000
#define NLOGB 4000        // k_logits blocks
#define PREF_BYTES ((size_t)24000 * H * 4)   // ~96 MB of W_out prefetched to L2

// ---------------- device scratch (no allocs allowed) ----------------
__device__ __align__(16) float g_gates[4 * H];
__device__ __align__(16) float g_h[H];
__device__ __align__(16) float g_u[H];
__device__ __align__(16) float g_scores[S];
__device__ __align__(16) float g_context[E];
__device__ __align__(16) float g_xt[H];
__device__ __align__(16) float g_C[(size_t)S * H];   // attention GEMM output (8 MB)
__device__ __align__(16) float g_lp[NLOGB];          // per-block exp-sum partials
__device__ float g_sumexp;                           // softmax denominator

__device__ __forceinline__ float sigf(float x) { return 1.0f / (1.0f + expf(-x)); }

__device__ __forceinline__ float warp_sum(float s) {
#pragma unroll
    for (int o = 16; o; o >>= 1) s += __shfl_xor_sync(0xFFFFFFFFu, s, o);
    return s;
}

__device__ __forceinline__ void mma_tf32(float* c, const uint32_t* a, uint32_t b0, uint32_t b1) {
    asm volatile(
        "mma.sync.aligned.m16n8k8.row.col.f32.tf32.tf32.f32 "
        "{%0,%1,%2,%3}, {%4,%5,%6,%7}, {%8,%9}, {%0,%1,%2,%3};\n"
        : "+f"(c[0]), "+f"(c[1]), "+f"(c[2]), "+f"(c[3])
        : "r"(a[0]), "r"(a[1]), "r"(a[2]), "r"(a[3]), "r"(b0), "r"(b1));
}

__device__ __forceinline__ void ldsm_x4(uint32_t* r, uint32_t addr) {
    asm volatile("ldmatrix.sync.aligned.m8n8.x4.shared.b16 {%0,%1,%2,%3}, [%4];"
                 : "=r"(r[0]), "=r"(r[1]), "=r"(r[2]), "=r"(r[3]) : "r"(addr));
}
__device__ __forceinline__ void ldsm_x2(uint32_t& r0, uint32_t& r1, uint32_t addr) {
    asm volatile("ldmatrix.sync.aligned.m8n8.x2.shared.b16 {%0,%1}, [%2];"
                 : "=r"(r0), "=r"(r1) : "r"(addr));
}

__device__ __forceinline__ void cp16(uint32_t dst_smem, const void* src) {
    asm volatile("cp.async.cg.shared.global [%0], [%1], 16;\n" :: "r"(dst_smem), "l"(src));
}
__device__ __forceinline__ void cp_commit() {
    asm volatile("cp.async.commit_group;\n");
}
template <int N>
__device__ __forceinline__ void cp_wait() {
    asm volatile("cp.async.wait_group %0;\n" :: "n"(N));
}

__device__ __forceinline__ float dot4(float4 a, float4 b) {
    return a.x * b.x + a.y * b.y + a.z * b.z + a.w * b.w;
}

// ---------------- K0: W_out prefetch into L2 (side stream, LAST before join) ------
__global__ void k_prefetch(const float* __restrict__ W_out) {
    const char* base = (const char*)W_out;
    size_t line = (size_t)blockIdx.x * 256 + threadIdx.x;
#pragma unroll
    for (int it = 0; it < 4; it++) {
        size_t off = (line + (size_t)it * 196608) * 128;
        if (off < PREF_BYTES)
            asm volatile("prefetch.global.L2 [%0];" :: "l"(base + off));
    }
}

// ---------------- K1: LSTM gates matvec (side stream, FIRST) ----------------
__global__ void k_gates(const float* __restrict__ W_ih, const float* __restrict__ b_ih,
                        const float* __restrict__ W_hh, const float* __restrict__ b_hh,
                        const float* __restrict__ last_ctx, const float* __restrict__ emb,
                        const int* __restrict__ word, const float* __restrict__ h0) {
    int r    = blockIdx.x * 8 + (threadIdx.x >> 5);
    int lane = threadIdx.x & 31;
    const float4* xe4 = (const float4*)(emb + (size_t)word[0] * E);
    const float4* lc4 = (const float4*)last_ctx;
    const float4* h04 = (const float4*)h0;
    const float4* wi4 = (const float4*)(W_ih + (size_t)r * (E + H));
    const float4* wh4 = (const float4*)(W_hh + (size_t)r * H);

    float s = 0.f;
#pragma unroll
    for (int q = 0; q < 8; q++) {
        int k = lane + 32 * q;
        s += dot4(wi4[k], lc4[k]) + dot4(wi4[256 + k], xe4[k]) + dot4(wh4[k], h04[k]);
    }
    s = warp_sum(s);
    if (lane == 0) g_gates[r] = s + b_ih[r] + b_hh[r];
}

// ---------------- K2: fused LSTM cell + u = W_att[:,:H]@h + b_att (side stream) ----
__global__ void k_cell_u(const float* __restrict__ c0, const float* __restrict__ W_att,
                         const float* __restrict__ b_att, float* __restrict__ out) {
    __shared__ float sh[H];
    int tid  = threadIdx.x;
    int wid  = tid >> 5;
    int lane = tid & 31;

#pragma unroll
    for (int j = 0; j < 4; j++) {
        int t = tid + 256 * j;
        float ig = sigf(g_gates[t]);
        float fg = sigf(g_gates[H + t]);
        float gg = tanhf(g_gates[2 * H + t]);
        float og = sigf(g_gates[3 * H + t]);
        float c  = fg * c0[t] + ig * gg;
        float h  = og * tanhf(c);
        sh[t] = h;
        if (blockIdx.x == 0) {
            g_h[t] = h;
            out[V + t]     = h;
            out[V + H + t] = c;
            g_context[t]   = 0.f;
        }
    }
    if (blockIdx.x == 0 && tid == 0) g_sumexp = 0.f;
    __syncthreads();

    int r = blockIdx.x * 8 + wid;
    const float4* wa4 = (const float4*)(W_att + (size_t)r * (H + E));
    const float4* h4  = (const float4*)sh;
    float s = 0.f;
#pragma unroll
    for (int q = 0; q < 8; q++) {
        int k = lane + 32 * q;
        s += dot4(wa4[k], h4[k]);
    }
    s = warp_sum(s);
    if (lane == 0) g_u[r] = s + b_att[r];
}

// ---------------- K3: attention GEMM (tf32 mma.sync + ldmatrix, cp.async 4-stage) ----
#define BM 64
#define BN 128
#define BKC 32
#define PADK 36
#define NSTAGE 4
#define NKC (E / BKC)
#define STAGE_FLOATS ((BM + BN) * PADK)
#define ATT_SMEM_BYTES (NSTAGE * STAGE_FLOATS * 4)

__global__ void __launch_bounds__(256, 2)
k_att_gemm(const float* __restrict__ enc, const float* __restrict__ W_att) {
    extern __shared__ float smem_dyn[];

    int tid  = threadIdx.x;
    int wid  = tid >> 5;
    int lane = tid & 31;
    int warp_m = wid >> 2;
    int warp_n = wid & 3;
    int gid  = lane >> 2;
    int tid4 = lane & 3;
    int s0 = blockIdx.x * BM;
    int h0 = blockIdx.y * BN;

    uint32_t smem_u32;
    {
        uint64_t tmp;
        asm("cvta.to.shared.u64 %0, %1;" : "=l"(tmp) : "l"(smem_dyn));
        smem_u32 = (uint32_t)tmp;
    }

    int la_row = (lane & 7) + ((lane >> 3) & 1) * 8;     // 0..15
    int la_kof = (lane >> 4) * 4;                        // 0 or 4
    int lb_row = lane & 7;
    int lb_kof = ((lane >> 3) & 1) * 4;

    float acc[2][4][4];
#pragma unroll
    for (int mt = 0; mt < 2; mt++)
#pragma unroll
        for (int nt = 0; nt < 4; nt++)
#pragma unroll
            for (int r = 0; r < 4; r++) acc[mt][nt][r] = 0.f;

    int rA[2], cA[2], rB[4], cB[4];
#pragma unroll
    for (int i = 0; i < 2; i++) { int f = tid + 256 * i; rA[i] = f >> 3; cA[i] = f & 7; }
#pragma unroll
    for (int i = 0; i < 4; i++) { int f = tid + 256 * i; rB[i] = f >> 3; cB[i] = f & 7; }

    const float* encp = enc   + (size_t)s0 * E;
    const float* wap  = W_att + (size_t)h0 * (H + E) + H;

#define ISSUE(kc_) do {                                                             \
        int st_ = (kc_) & (NSTAGE - 1);                                             \
        uint32_t abase_ = smem_u32 + st_ * (STAGE_FLOATS * 4);                      \
        uint32_t bbase_ = abase_ + BM * PADK * 4;                                   \
        int kofs_ = (kc_) * BKC;                                                    \
        _Pragma("unroll")                                                           \
        for (int i = 0; i < 2; i++)                                                 \
            cp16(abase_ + (rA[i] * PADK + cA[i] * 4) * 4,                           \
                 encp + (size_t)rA[i] * E + kofs_ + cA[i] * 4);                     \
        _Pragma("unroll")                                                           \
        for (int i = 0; i < 4; i++)                                                 \
            cp16(bbase_ + (rB[i] * PADK + cB[i] * 4) * 4,                           \
                 wap + (size_t)rB[i] * (H + E) + kofs_ + cB[i] * 4);                \
        cp_commit();                                                                \
    } while (0)

    ISSUE(0); ISSUE(1); ISSUE(2);

    for (int kc = 0; kc < NKC; kc++) {
        cp_wait<2>();
        __syncthreads();
        if (kc + 3 < NKC) ISSUE(kc + 3);

        int st = kc & (NSTAGE - 1);
        uint32_t abase = smem_u32 + st * (STAGE_FLOATS * 4);
        uint32_t bbase = abase + BM * PADK * 4;
        uint32_t aaddr0 = abase + (((warp_m * 32 + la_row) * PADK) + la_kof) * 4;
        uint32_t baddr0 = bbase + (((warp_n * 32 + lb_row) * PADK) + lb_kof) * 4;

#pragma unroll
        for (int ks = 0; ks < BKC / 8; ks++) {
            int kb = ks * 8;
            uint32_t af[2][4];
#pragma unroll
            for (int mt = 0; mt < 2; mt++)
                ldsm_x4(af[mt], aaddr0 + (mt * 16 * PADK + kb) * 4);
#pragma unroll
            for (int nt = 0; nt < 4; nt++) {
                uint32_t b0, b1;
                ldsm_x2(b0, b1, baddr0 + (nt * 8 * PADK + kb) * 4);
#pragma unroll
                for (int mt = 0; mt < 2; mt++)
                    mma_tf32(acc[mt][nt], af[mt], b0, b1);
            }
        }
    }
#undef ISSUE

#pragma unroll
    for (int mt = 0; mt < 2; mt++) {
        int srow = s0 + warp_m * 32 + mt * 16 + gid;
#pragma unroll
        for (int nt = 0; nt < 4; nt++) {
            int hcol = h0 + warp_n * 32 + nt * 8 + 2 * tid4;
            float2 v0 = make_float2(acc[mt][nt][0], acc[mt][nt][1]);
            float2 v1 = make_float2(acc[mt][nt][2], acc[mt][nt][3]);
            *(float2*)&g_C[(size_t)srow * H + hcol]       = v0;
            *(float2*)&g_C[(size_t)(srow + 8) * H + hcol] = v1;
        }
    }
}

// ---------------- K4: score epilogue: warp-per-row + global exp-sum atomic ----
__global__ void k_score(const float* __restrict__ v) {
    int wid  = threadIdx.x >> 5;
    int lane = threadIdx.x & 31;
    int row  = blockIdx.x * 8 + wid;

    const float4* c4 = (const float4*)(g_C + (size_t)row * H);
    const float4* u4 = (const float4*)g_u;
    const float4* v4 = (const float4*)v;

    float p = 0.f;
#pragma unroll
    for (int q = 0; q < 8; q++) {
        int k = lane + 32 * q;
        float4 c = c4[k]; float4 u = u4[k]; float4 vv = v4[k];
        p += vv.x * tanhf(c.x + u.x) + vv.y * tanhf(c.y + u.y)
           + vv.z * tanhf(c.z + u.z) + vv.w * tanhf(c.w + u.w);
    }
    p = warp_sum(p);
    if (lane == 0) {
        g_scores[row] = p;
        atomicAdd(&g_sumexp, expf(p));    // scores bounded by ~51 -> no overflow
    }
}

// ---------------- K5: context = softmax(scores) @ enc  (float4, 16-s slabs) ----------
__global__ void k_ctx(const float* __restrict__ enc, float* __restrict__ out) {
    __shared__ float sw[16];
    int tid = threadIdx.x;
    int s0c = blockIdx.x * 16;
    if (tid < 16) {
        float w = expf(g_scores[s0c + tid]) / g_sumexp;
        sw[tid] = w;
        out[V + 3 * H + s0c + tid] = w;
    }
    __syncthreads();
    const float4* e4 = (const float4*)enc;
    float4 acc = make_float4(0.f, 0.f, 0.f, 0.f);
#pragma unroll
    for (int s = 0; s < 16; s++) {
        float w = sw[s];
        float4 ev = e4[(size_t)(s0c + s) * 256 + tid];
        acc.x += w * ev.x; acc.y += w * ev.y; acc.z += w * ev.z; acc.w += w * ev.w;
    }
    atomicAdd(&g_context[tid * 4 + 0], acc.x);
    atomicAdd(&g_context[tid * 4 + 1], acc.y);
    atomicAdd(&g_context[tid * 4 + 2], acc.z);
    atomicAdd(&g_context[tid * 4 + 3], acc.w);
}

// ---------------- K6: x_t = tanh(W_ah @ [context, h] + b_ah) ----------------
__global__ void k_xt(const float* __restrict__ W_ah, const float* __restrict__ b_ah,
                     float* __restrict__ out) {
    int r    = blockIdx.x * 8 + (threadIdx.x >> 5);
    int lane = threadIdx.x & 31;
    const float4* wa4 = (const float4*)(W_ah + (size_t)r * (E + H));
    const float4* c4  = (const float4*)g_context;
    const float4* h4  = (const float4*)g_h;
    float s = 0.f;
#pragma unroll
    for (int q = 0; q < 8; q++) {
        int k = lane + 32 * q;
        s += dot4(wa4[k], c4[k]) + dot4(wa4[256 + k], h4[k]);
    }
    s = warp_sum(s);
    if (lane == 0) {
        float xt = tanhf(s + b_ah[r]);
        g_xt[r] = xt;
        out[V + 2 * H + r] = xt;
    }
}

// ---------------- K7: logits = W_out @ x_t + b_out, + per-block exp-sum partials ----
__global__ void k_logits(const float* __restrict__ W_out, const float* __restrict__ b_out,
                         float* __restrict__ out) {
    __shared__ float sred[8];
    int tid  = threadIdx.x;
    int wid  = tid >> 5;
    int lane = tid & 31;
    int r    = blockIdx.x * 8 + wid;
    const float4* w4 = (const float4*)(W_out + (size_t)r * H);
    const float4* x4 = (const float4*)g_xt;
    float s = 0.f;
#pragma unroll
    for (int q = 0; q < 8; q++) {
        int k = lane + 32 * q;
        s += dot4(w4[k], x4[k]);
    }
    s = warp_sum(s);
    if (lane == 0) {
        float val = s + b_out[r];
        out[r] = val;
        sred[wid] = expf(val);
    }
    __syncthreads();
    if (tid == 0) {
        float p = 0.f;
#pragma unroll
        for (int i = 0; i < 8; i++) p += sred[i];
        g_lp[blockIdx.x] = p;
    }
}

// ---------------- K8: log-softmax ----------------
__global__ void k_logsoftmax(float* __restrict__ out) {
    __shared__ float red[256];
    int tid = threadIdx.x;
    float p = 0.f;
    for (int i = tid; i < NLOGB; i += 256) p += g_lp[i];
    red[tid] = p; __syncthreads();
    for (int o = 128; o; o >>= 1) { if (tid < o) red[tid] += red[tid + o]; __syncthreads(); }
    float l = logf(red[0]);
    int i = blockIdx.x * 256 + tid;
    out[i] = out[i] - l;
}

// ---------------- launch (R11-identical allocation footprint: 1 stream, 2 events) ----
extern "C" void kernel_launch(void* const* d_in, const int* in_sizes, int n_in,
                              void* d_out, int out_size) {
    const float* enc      = (const float*)d_in[0];
    const int*   word     = (const int*)  d_in[1];
    const float* last_ctx = (const float*)d_in[2];
    const float* h0       = (const float*)d_in[3];
    const float* c0       = (const float*)d_in[4];
    const float* emb      = (const float*)d_in[5];
    const float* W_ih     = (const float*)d_in[6];
    const float* b_ih     = (const float*)d_in[7];
    const float* W_hh     = (const float*)d_in[8];
    const float* b_hh     = (const float*)d_in[9];
    const float* W_att    = (const float*)d_in[10];
    const float* b_att    = (const float*)d_in[11];
    const float* v        = (const float*)d_in[12];
    const float* W_ah     = (const float*)d_in[13];
    const float* b_ah     = (const float*)d_in[14];
    const float* W_out    = (const float*)d_in[15];
    const float* b_out    = (const float*)d_in[16];
    float* out = (float*)d_out;

    cudaFuncSetAttribute(k_att_gemm, cudaFuncAttributeMaxDynamicSharedMemorySize, ATT_SMEM_BYTES);

    // fork: gates -> cell_u -> prefetch on side stream (prefetch LAST so W_out
    // survives in L2), attention GEMM on main stream
    cudaStream_t sB;
    cudaStreamCreateWithFlags(&sB, cudaStreamNonBlocking);
    cudaEvent_t e0, eB;
    cudaEventCreateWithFlags(&e0, cudaEventDisableTiming);
    cudaEventCreateWithFlags(&eB, cudaEventDisableTiming);

    cudaEventRecord(e0, 0);
    cudaStreamWaitEvent(sB, e0, 0);
    k_gates<<<512, 256, 0, sB>>>(W_ih, b_ih, W_hh, b_hh, last_ctx, emb, word, h0);
    k_cell_u<<<128, 256, 0, sB>>>(c0, W_att, b_att, out);
    k_prefetch<<<768, 256, 0, sB>>>(W_out);
    cudaEventRecord(eB, sB);

    dim3 g3(S / BM, H / BN);
    k_att_gemm<<<g3, 256, ATT_SMEM_BYTES>>>(enc, W_att);

    cudaStreamWaitEvent(0, eB, 0);
    k_score<<<S / 8, 256>>>(v);
    k_ctx<<<S / 16, 256>>>(enc, out);
    k_xt<<<128, 256>>>(W_ah, b_ah, out);
    k_logits<<<NLOGB, 256>>>(W_out, b_out, out);
    k_logsoftmax<<<V / 256, 256>>>(out);
}